// round 16
// baseline (speedup 1.0000x reference)
#include <cuda_runtime.h>
#include <cuda_bf16.h>

// HarmonicLowering: out[b, k*32+c, f, t] = w * x[b,c,idx,t] + (1-w) * x[b,c,idx1,t]
//   k in 1..4, idx = (f*k)>>2, w = 1 - (f*k & 3)*0.25, idx1 = min(idx+1, 255)
// x = (8, 32, 256, 512) f32 (128 MiB); out = (8, 128, 256, 512) f32 (512 MiB).
//
// R7:  L1tex 82% limiter (lane-stride-2 from thread-consecutive VPT=2).
// R14: grid-split halves -> lane-stride-1 everywhere. 121.7 -> 111.4 us,
//      L1 57.9%, DRAM 76.5%, nothing saturated => latency-exposed.
// R15: VPT=4 grid-split quarters, all 8 loads front-batched (MLP=8) to fill
//      the DRAM pipe. Every access still lane-stride-1 / 512B-per-warp.

static constexpr int B = 8;
static constexpr int C = 32;
static constexpr int F = 256;
static constexpr int T4 = 128;            // 512 floats / 4
static constexpr unsigned int OUT_V4 = (unsigned int)B * 4 * C * F * T4;  // 33,554,432
static constexpr unsigned int QUARTER_V4 = OUT_V4 / 4;                    // 8,388,608

__global__ void __launch_bounds__(256) harmonic_lowering_kernel(
    const float4* __restrict__ x, float4* __restrict__ out)
{
    unsigned int i0 = blockIdx.x * blockDim.x + threadIdx.x;   // < 2^23

    unsigned int iv[4];
    float4 g0v[4], g1v[4];
    float wv[4];

    // Front-batch all 8 loads: compute indices + issue LDGs, no consumption yet.
#pragma unroll
    for (int v = 0; v < 4; ++v) {
        unsigned int i = i0 + (unsigned int)v * QUARTER_V4;
        iv[v] = i;

        // output v4 index decomposition: (((b*128 + kc)*256 + f)*128 + t4)
        unsigned int t4 = i & 127u;
        unsigned int f  = (i >> 7) & 255u;
        unsigned int kc = (i >> 15) & 127u;
        unsigned int b  = i >> 22;

        unsigned int k  = (kc >> 5) + 1u;     // 1..4
        unsigned int ch = kc & 31u;

        unsigned int prod = f * k;
        unsigned int idx  = prod >> 2;
        wv[v] = 1.0f - (float)(prod & 3u) * 0.25f;
        unsigned int idx1 = min(idx + 1u, (unsigned int)(F - 1));

        unsigned int base = (b * C + ch) * F;             // row index into x
        g0v[v] = x[((base + idx ) << 7) + t4];
        g1v[v] = x[((base + idx1) << 7) + t4];
    }

#pragma unroll
    for (int v = 0; v < 4; ++v) {
        float w  = wv[v];
        float wm = 1.0f - w;
        float4 o;
        o.x = fmaf(w, g0v[v].x, wm * g1v[v].x);
        o.y = fmaf(w, g0v[v].y, wm * g1v[v].y);
        o.z = fmaf(w, g0v[v].z, wm * g1v[v].z);
        o.w = fmaf(w, g0v[v].w, wm * g1v[v].w);
        out[iv[v]] = o;
    }
}

extern "C" void kernel_launch(void* const* d_in, const int* in_sizes, int n_in,
                              void* d_out, int out_size)
{
    const float4* x = (const float4*)d_in[0];
    float4* out = (float4*)d_out;
    const int threads = 256;
    const int blocks = (int)(QUARTER_V4 / threads);       // 32768
    harmonic_lowering_kernel<<<blocks, threads>>>(x, out);
}